// round 1
// baseline (speedup 1.0000x reference)
#include <cuda_runtime.h>

// Problem constants
#define BN_  4
#define C_   256
#define NPX_ 4096    // 64*64
#define O_   64
#define G_   16
#define GC_  16

typedef unsigned long long ull;

// --------- scratch (allocation-free: __device__ globals) ----------
__device__ float g_w1t[C_ * O_];        // [c][o], BN-folded, transposed
__device__ float g_b1[O_];              // BN-folded bias
__device__ float g_t[BN_ * NPX_ * O_];  // t tensor, [b][px][o], 4 MB

// --------- f32x2 helpers (Blackwell packed fp32) ----------
__device__ __forceinline__ ull pk(float a, float b) {
    ull r; asm("mov.b64 %0,{%1,%2};" : "=l"(r) : "f"(a), "f"(b)); return r;
}
__device__ __forceinline__ ull dupf(float a) {
    ull r; asm("mov.b64 %0,{%1,%1};" : "=l"(r) : "f"(a)); return r;
}
__device__ __forceinline__ void fma2(ull& d, ull a, ull b) {
    asm("fma.rn.f32x2 %0,%1,%2,%0;" : "+l"(d) : "l"(a), "l"(b));
}
__device__ __forceinline__ void unpk(ull v, float& a, float& b) {
    asm("mov.b64 {%0,%1},%2;" : "=f"(a), "=f"(b) : "l"(v));
}

// =================================================================
// Prep: fold BN into conv1 weights, store transposed [c][o]
// =================================================================
__global__ void prep_kernel(const float* __restrict__ w1,
                            const float* __restrict__ gamma,
                            const float* __restrict__ beta,
                            const float* __restrict__ mean,
                            const float* __restrict__ var) {
    int i = blockIdx.x * blockDim.x + threadIdx.x;
    if (i >= C_ * O_) return;
    int c = i / O_, o = i % O_;
    float sc = gamma[o] * rsqrtf(var[o] + 1e-5f);
    g_w1t[c * O_ + o] = w1[o * C_ + c] * sc;
    if (c == 0) g_b1[o] = beta[o] - mean[o] * sc;
}

// =================================================================
// conv1: t[bpx][o] = relu( sum_c w1t[c][o] * x[b][c][px] + b1[o] )
// Block: 64 pixels x 64 o. Thread: 4px x 4o, f32x2 over px pairs.
// =================================================================
__global__ __launch_bounds__(256) void conv1_kernel(const float* __restrict__ x) {
    __shared__ float xs[32 * 64];  // [c][px]
    __shared__ float ws[32 * 68];  // [c][o] (+pad)

    int tid = threadIdx.x;
    int bpx0 = blockIdx.x * 64;                       // global pixel base
    const float* xb = x + (size_t)(bpx0 / NPX_) * C_ * NPX_ + (bpx0 % NPX_);

    int to = tid & 15, tp = tid >> 4;
    int p0 = tp * 4, o0 = to * 4;

    ull acc[2][4];
#pragma unroll
    for (int pp = 0; pp < 2; pp++)
#pragma unroll
        for (int oi = 0; oi < 4; oi++) acc[pp][oi] = 0ull;

    for (int cc = 0; cc < C_; cc += 32) {
#pragma unroll
        for (int i = 0; i < 8; i++) {
            int idx = tid + i * 256;
            int c = idx >> 6, low = idx & 63;
            xs[c * 64 + low] = xb[(size_t)(cc + c) * NPX_ + low];
            ws[c * 68 + low] = g_w1t[(cc + c) * O_ + low];
        }
        __syncthreads();
#pragma unroll
        for (int c = 0; c < 32; c++) {
            ulonglong2 av = *(const ulonglong2*)&xs[c * 64 + p0];
            float4 wv = *(const float4*)&ws[c * 68 + o0];
            ull b0 = dupf(wv.x), b1v = dupf(wv.y), b2v = dupf(wv.z), b3v = dupf(wv.w);
            fma2(acc[0][0], av.x, b0);  fma2(acc[1][0], av.y, b0);
            fma2(acc[0][1], av.x, b1v); fma2(acc[1][1], av.y, b1v);
            fma2(acc[0][2], av.x, b2v); fma2(acc[1][2], av.y, b2v);
            fma2(acc[0][3], av.x, b3v); fma2(acc[1][3], av.y, b3v);
        }
        __syncthreads();
    }

    float bias[4];
#pragma unroll
    for (int oi = 0; oi < 4; oi++) bias[oi] = g_b1[o0 + oi];

#pragma unroll
    for (int pp = 0; pp < 2; pp++) {
        float vA[4], vB[4];
#pragma unroll
        for (int oi = 0; oi < 4; oi++) {
            float a, b;
            unpk(acc[pp][oi], a, b);
            vA[oi] = fmaxf(a + bias[oi], 0.f);
            vB[oi] = fmaxf(b + bias[oi], 0.f);
        }
        int pxA = p0 + 2 * pp, pxB = pxA + 1;
        *(float4*)&g_t[(size_t)(bpx0 + pxA) * O_ + o0] = make_float4(vA[0], vA[1], vA[2], vA[3]);
        *(float4*)&g_t[(size_t)(bpx0 + pxB) * O_ + o0] = make_float4(vB[0], vB[1], vB[2], vB[3]);
    }
}

// =================================================================
// Fused conv2 + involution.
// Block = (batch, 8x8 spatial tile). Loops over 16 groups:
//   - stage 16-channel x halo (14x14) + w2 group slice in smem
//   - conv2: wt[px][k] = sum_o w2[g*49+k][o]*t[px][o] + b2  (f32x2 k-pairs)
//   - involution: out[c] = sum_k wt[k]*x[c, shifted]        (f32x2 px-pairs)
// =================================================================
#define TS_STRIDE 65           // t_s row stride (bank-conflict-free)
#define XG_CH 232              // xg channel stride (14 rows * 16 + 8 pad)
#define KPAD 56                // padded kernel count (49 -> 56)
#define SM_T   0
#define SM_XG  (64 * TS_STRIDE)
#define SM_W2  (SM_XG + 16 * XG_CH)
#define SM_WT  (SM_W2 + 64 * KPAD)
#define SM_TOT (SM_WT + KPAD * 64)
#define SMEM_BYTES (SM_TOT * 4)

__global__ __launch_bounds__(256) void inv_kernel(const float* __restrict__ x,
                                                  const float* __restrict__ w2,
                                                  const float* __restrict__ b2,
                                                  float* __restrict__ out) {
    extern __shared__ float sm[];
    float* t_s  = sm + SM_T;    // [64px][65]
    float* xg   = sm + SM_XG;   // [16c][232]
    float* w2s  = sm + SM_W2;   // [64o][56k]
    float* wt_s = sm + SM_WT;   // [56k][64px]

    int tid = threadIdx.x;
    int b = blockIdx.x >> 6;
    int tile = blockIdx.x & 63;
    int y0 = (tile >> 3) * 8, x0 = (tile & 7) * 8;
    const float* xb = x + (size_t)b * C_ * NPX_;

    // load t tile (64 px x 64 o), coalesced over o
#pragma unroll
    for (int i = 0; i < 16; i++) {
        int idx = tid + i * 256;
        int pxl = idx >> 6, o = idx & 63;
        int r = pxl >> 3, cx = pxl & 7;
        t_s[pxl * TS_STRIDE + o] =
            g_t[((size_t)b * NPX_ + (y0 + r) * 64 + (x0 + cx)) * O_ + o];
    }

    // conv2 thread coords: kq 0..7 (active <7), pq 0..31 -> pixels pq, pq+32
    int kq = tid >> 5, pq = tid & 31;
    // involution thread coords: 16 pxq (4 adjacent-x pixels) x 16 channels
    int pxq = tid & 15, ci = tid >> 4;
    int yloc = pxq >> 1, x0loc = (pxq & 1) * 4;

    for (int g = 0; g < G_; g++) {
        __syncthreads();  // protect t_s (g==0) / previous-group smem

        // stage x group halo (14x14 per channel, zero-padded)
        for (int idx = tid; idx < 16 * 196; idx += 256) {
            int c = idx / 196, rem = idx - c * 196;
            int rr = rem / 14, xx = rem - rr * 14;
            int gy = y0 + rr - 3, gx = x0 + xx - 3;
            float v = 0.f;
            if (gy >= 0 && gy < 64 && gx >= 0 && gx < 64)
                v = xb[(size_t)(g * GC_ + c) * NPX_ + gy * 64 + gx];
            xg[c * XG_CH + rr * 16 + xx] = v;
        }
        // stage w2 slice transposed: w2s[o][k]
        for (int idx = tid; idx < 64 * KPAD; idx += 256) {
            int k = idx >> 6, o = idx & 63;
            float v = (k < 49) ? w2[(size_t)(g * 49 + k) * O_ + o] : 0.f;
            w2s[o * KPAD + k] = v;
        }
        __syncthreads();

        // ---- conv2: 2 pixels x 8 k per thread, f32x2 over k-pairs ----
        if (kq < 7) {
            int k0 = kq * 8;
            ull accA[4], accB[4];
#pragma unroll
            for (int j = 0; j < 4; j++) {
                int ka = k0 + 2 * j, kb = ka + 1;
                float ba = (ka < 49) ? b2[g * 49 + ka] : 0.f;
                float bb = (kb < 49) ? b2[g * 49 + kb] : 0.f;
                accA[j] = pk(ba, bb);
                accB[j] = accA[j];
            }
#pragma unroll 8
            for (int o = 0; o < 64; o++) {
                ulonglong2 w01 = *(const ulonglong2*)&w2s[o * KPAD + k0];
                ulonglong2 w23 = *(const ulonglong2*)&w2s[o * KPAD + k0 + 4];
                ull da = dupf(t_s[pq * TS_STRIDE + o]);
                ull db = dupf(t_s[(pq + 32) * TS_STRIDE + o]);
                fma2(accA[0], w01.x, da); fma2(accA[1], w01.y, da);
                fma2(accA[2], w23.x, da); fma2(accA[3], w23.y, da);
                fma2(accB[0], w01.x, db); fma2(accB[1], w01.y, db);
                fma2(accB[2], w23.x, db); fma2(accB[3], w23.y, db);
            }
#pragma unroll
            for (int j = 0; j < 4; j++) {
                float a0, a1, b0, b1;
                unpk(accA[j], a0, a1);
                unpk(accB[j], b0, b1);
                wt_s[(k0 + 2 * j) * 64 + pq]          = a0;
                wt_s[(k0 + 2 * j + 1) * 64 + pq]      = a1;
                wt_s[(k0 + 2 * j) * 64 + pq + 32]     = b0;
                wt_s[(k0 + 2 * j + 1) * 64 + pq + 32] = b1;
            }
        }
        __syncthreads();

        // ---- involution: 4 adjacent-x pixels x 1 channel per thread ----
        {
            ull acc01 = 0ull, acc23 = 0ull;
            int px0 = pxq * 4;
            const float* xgc = xg + ci * XG_CH;
#pragma unroll
            for (int ky = 0; ky < 7; ky++) {
                const float* rowp = xgc + (yloc + ky) * 16 + x0loc;
                float4 rA = *(const float4*)rowp;
                float4 rB = *(const float4*)(rowp + 4);
                float2 rC = *(const float2*)(rowp + 8);
                float xr[10] = {rA.x, rA.y, rA.z, rA.w,
                                rB.x, rB.y, rB.z, rB.w,
                                rC.x, rC.y};
#pragma unroll
                for (int kx = 0; kx < 7; kx++) {
                    int k = ky * 7 + kx;
                    ull wt01 = *(const ull*)&wt_s[k * 64 + px0];
                    ull wt23 = *(const ull*)&wt_s[k * 64 + px0 + 2];
                    fma2(acc01, wt01, pk(xr[kx], xr[kx + 1]));
                    fma2(acc23, wt23, pk(xr[kx + 2], xr[kx + 3]));
                }
            }
            float v0, v1, v2, v3;
            unpk(acc01, v0, v1);
            unpk(acc23, v2, v3);
            int gy = y0 + yloc, gx = x0 + x0loc;
            *(float4*)&out[((size_t)b * C_ + g * GC_ + ci) * NPX_ + gy * 64 + gx] =
                make_float4(v0, v1, v2, v3);
        }
    }
}

// =================================================================
extern "C" void kernel_launch(void* const* d_in, const int* in_sizes, int n_in,
                              void* d_out, int out_size) {
    const float* x     = (const float*)d_in[0];
    const float* w1    = (const float*)d_in[1];
    const float* gamma = (const float*)d_in[2];
    const float* beta  = (const float*)d_in[3];
    const float* mean  = (const float*)d_in[4];
    const float* var   = (const float*)d_in[5];
    const float* w2    = (const float*)d_in[6];
    const float* b2    = (const float*)d_in[7];
    float* out = (float*)d_out;

    cudaFuncSetAttribute(inv_kernel, cudaFuncAttributeMaxDynamicSharedMemorySize,
                         SMEM_BYTES);

    prep_kernel<<<64, 256>>>(w1, gamma, beta, mean, var);
    conv1_kernel<<<256, 256>>>(x);
    inv_kernel<<<256, 256, SMEM_BYTES>>>(x, w2, b2, out);
}

// round 2
// speedup vs baseline: 1.0628x; 1.0628x over previous
#include <cuda_runtime.h>

// Problem constants
#define BN_  4
#define C_   256
#define NPX_ 4096    // 64*64
#define O_   64
#define G_   16
#define GC_  16
#define GS_  4       // group-split factor for inv kernel (4 groups/block)

typedef unsigned long long ull;

// --------- scratch (allocation-free: __device__ global) ----------
__device__ float g_t[BN_ * NPX_ * O_];  // t tensor, [b][px][o], 4 MB

// --------- f32x2 helpers (Blackwell packed fp32) ----------
__device__ __forceinline__ ull pk(float a, float b) {
    ull r; asm("mov.b64 %0,{%1,%2};" : "=l"(r) : "f"(a), "f"(b)); return r;
}
__device__ __forceinline__ ull dupf(float a) {
    ull r; asm("mov.b64 %0,{%1,%1};" : "=l"(r) : "f"(a)); return r;
}
__device__ __forceinline__ void fma2(ull& d, ull a, ull b) {
    asm("fma.rn.f32x2 %0,%1,%2,%0;" : "+l"(d) : "l"(a), "l"(b));
}
__device__ __forceinline__ void unpk(ull v, float& a, float& b) {
    asm("mov.b64 {%0,%1},%2;" : "=f"(a), "=f"(b) : "l"(v));
}

// =================================================================
// conv1 (BN folded in-kernel): t[bpx][o] = relu(sum_c w1[o][c]*sc[o]*x + b1[o])
// Block: 32 pixels x 64 o, 512 blocks. Thread: 2px (one f32x2 pair) x 4o.
// =================================================================
__global__ __launch_bounds__(256) void conv1_kernel(const float* __restrict__ x,
                                                    const float* __restrict__ w1,
                                                    const float* __restrict__ gamma,
                                                    const float* __restrict__ beta,
                                                    const float* __restrict__ mean,
                                                    const float* __restrict__ var) {
    __shared__ __align__(16) float xs[32 * 32];  // [c][px]
    __shared__ __align__(16) float ws[32 * 68];  // [c][o] (+pad)
    __shared__ float sc_s[64], b1_s[64];

    int tid = threadIdx.x;
    int bpx0 = blockIdx.x * 32;                       // global pixel base
    const float* xb = x + (size_t)(bpx0 / NPX_) * C_ * NPX_ + (bpx0 % NPX_);

    if (tid < 64) {
        float sc = gamma[tid] * rsqrtf(var[tid] + 1e-5f);
        sc_s[tid] = sc;
        b1_s[tid] = beta[tid] - mean[tid] * sc;
    }
    __syncthreads();

    int to = tid & 15, tp = tid >> 4;
    int p0 = tp * 2, o0 = to * 4;

    ull acc[4] = {0ull, 0ull, 0ull, 0ull};

    for (int cc = 0; cc < C_; cc += 32) {
        __syncthreads();
        // x tile: 32c x 32px, coalesced over px
#pragma unroll
        for (int i = 0; i < 4; i++) {
            int idx = tid + i * 256;
            int c = idx >> 5, low = idx & 31;
            xs[c * 32 + low] = xb[(size_t)(cc + c) * NPX_ + low];
        }
        // w tile: 32c x 64o, read coalesced over c, scatter to [c][o], fold BN
#pragma unroll
        for (int i = 0; i < 8; i++) {
            int idx = tid + i * 256;
            int o = idx >> 5, cl = idx & 31;
            ws[cl * 68 + o] = w1[(size_t)o * C_ + cc + cl] * sc_s[o];
        }
        __syncthreads();
#pragma unroll
        for (int c = 0; c < 32; c++) {
            ull av = *(const ull*)&xs[c * 32 + p0];
            float4 wv = *(const float4*)&ws[c * 68 + o0];
            fma2(acc[0], av, dupf(wv.x));
            fma2(acc[1], av, dupf(wv.y));
            fma2(acc[2], av, dupf(wv.z));
            fma2(acc[3], av, dupf(wv.w));
        }
    }

    float vA[4], vB[4];
#pragma unroll
    for (int oi = 0; oi < 4; oi++) {
        float a, b;
        unpk(acc[oi], a, b);
        float bias = b1_s[o0 + oi];
        vA[oi] = fmaxf(a + bias, 0.f);
        vB[oi] = fmaxf(b + bias, 0.f);
    }
    *(float4*)&g_t[(size_t)(bpx0 + p0) * O_ + o0]     = make_float4(vA[0], vA[1], vA[2], vA[3]);
    *(float4*)&g_t[(size_t)(bpx0 + p0 + 1) * O_ + o0] = make_float4(vB[0], vB[1], vB[2], vB[3]);
}

// =================================================================
// Fused conv2 + involution, group-split 4-way (grid = 4*64*4 = 1024).
// Block = (batch, 8x8 spatial tile, 4-group chunk):
//   - stage 16-channel x halo (14x14) + w2 group slice in smem
//   - conv2: wt[px][k] = sum_o w2[g*49+k][o]*t[px][o] + b2  (f32x2 k-pairs)
//   - involution: out[c] = sum_k wt[k]*x[c, shifted]        (f32x2 px-pairs)
// =================================================================
#define TS_STRIDE 65           // t_s row stride (bank-conflict-free)
#define XG_CH 232              // xg channel stride (14 rows * 16 + 8 pad)
#define KPAD 56                // padded kernel count (49 -> 56)
#define SM_T   0
#define SM_XG  (64 * TS_STRIDE)
#define SM_W2  (SM_XG + 16 * XG_CH)
#define SM_WT  (SM_W2 + 64 * KPAD)
#define SM_TOT (SM_WT + KPAD * 64)
#define SMEM_BYTES (SM_TOT * 4)

__global__ __launch_bounds__(256) void inv_kernel(const float* __restrict__ x,
                                                  const float* __restrict__ w2,
                                                  const float* __restrict__ b2,
                                                  float* __restrict__ out) {
    extern __shared__ __align__(16) float sm[];
    float* t_s  = sm + SM_T;    // [64px][65]
    float* xg   = sm + SM_XG;   // [16c][232]
    float* w2s  = sm + SM_W2;   // [64o][56k]
    float* wt_s = sm + SM_WT;   // [56k][64px]

    int tid = threadIdx.x;
    int bid = blockIdx.x;
    int gs = bid & (GS_ - 1);
    int tile = (bid >> 2) & 63;
    int b = bid >> 8;
    int y0 = (tile >> 3) * 8, x0 = (tile & 7) * 8;
    const float* xb = x + (size_t)b * C_ * NPX_;

    // load t tile (64 px x 64 o), coalesced over o
#pragma unroll
    for (int i = 0; i < 16; i++) {
        int idx = tid + i * 256;
        int pxl = idx >> 6, o = idx & 63;
        int r = pxl >> 3, cx = pxl & 7;
        t_s[pxl * TS_STRIDE + o] =
            g_t[((size_t)b * NPX_ + (y0 + r) * 64 + (x0 + cx)) * O_ + o];
    }

    // conv2 thread coords: kq 0..7 (active <7), pq 0..31 -> pixels pq, pq+32
    int kq = tid >> 5, pq = tid & 31;
    // involution thread coords: 16 pxq (4 adjacent-x pixels) x 16 channels
    int pxq = tid & 15, ci = tid >> 4;
    int yloc = pxq >> 1, x0loc = (pxq & 1) * 4;

#pragma unroll 1
    for (int gi = 0; gi < G_ / GS_; gi++) {
        int g = gs * (G_ / GS_) + gi;
        __syncthreads();  // protect t_s (gi==0) / previous-group smem

        // stage x group halo (14x14 per channel, zero-padded)
        for (int idx = tid; idx < 16 * 196; idx += 256) {
            int c = idx / 196, rem = idx - c * 196;
            int rr = rem / 14, xx = rem - rr * 14;
            int gy = y0 + rr - 3, gx = x0 + xx - 3;
            float v = 0.f;
            if (gy >= 0 && gy < 64 && gx >= 0 && gx < 64)
                v = xb[(size_t)(g * GC_ + c) * NPX_ + gy * 64 + gx];
            xg[c * XG_CH + rr * 16 + xx] = v;
        }
        // stage w2 slice transposed: w2s[o][k]
        for (int idx = tid; idx < 64 * KPAD; idx += 256) {
            int k = idx >> 6, o = idx & 63;
            float v = (k < 49) ? w2[(size_t)(g * 49 + k) * O_ + o] : 0.f;
            w2s[o * KPAD + k] = v;
        }
        __syncthreads();

        // ---- conv2: 2 pixels x 8 k per thread, f32x2 over k-pairs ----
        if (kq < 7) {
            int k0 = kq * 8;
            ull accA[4], accB[4];
#pragma unroll
            for (int j = 0; j < 4; j++) {
                int ka = k0 + 2 * j, kb = ka + 1;
                float ba = (ka < 49) ? b2[g * 49 + ka] : 0.f;
                float bb = (kb < 49) ? b2[g * 49 + kb] : 0.f;
                accA[j] = pk(ba, bb);
                accB[j] = accA[j];
            }
#pragma unroll 8
            for (int o = 0; o < 64; o++) {
                ulonglong2 w01 = *(const ulonglong2*)&w2s[o * KPAD + k0];
                ulonglong2 w23 = *(const ulonglong2*)&w2s[o * KPAD + k0 + 4];
                ull da = dupf(t_s[pq * TS_STRIDE + o]);
                ull db = dupf(t_s[(pq + 32) * TS_STRIDE + o]);
                fma2(accA[0], w01.x, da); fma2(accA[1], w01.y, da);
                fma2(accA[2], w23.x, da); fma2(accA[3], w23.y, da);
                fma2(accB[0], w01.x, db); fma2(accB[1], w01.y, db);
                fma2(accB[2], w23.x, db); fma2(accB[3], w23.y, db);
            }
#pragma unroll
            for (int j = 0; j < 4; j++) {
                float a0, a1, b0, b1;
                unpk(accA[j], a0, a1);
                unpk(accB[j], b0, b1);
                wt_s[(k0 + 2 * j) * 64 + pq]          = a0;
                wt_s[(k0 + 2 * j + 1) * 64 + pq]      = a1;
                wt_s[(k0 + 2 * j) * 64 + pq + 32]     = b0;
                wt_s[(k0 + 2 * j + 1) * 64 + pq + 32] = b1;
            }
        }
        __syncthreads();

        // ---- involution: 4 adjacent-x pixels x 1 channel per thread ----
        {
            ull acc01 = 0ull, acc23 = 0ull;
            int px0 = pxq * 4;
            const float* xgc = xg + ci * XG_CH;
#pragma unroll
            for (int ky = 0; ky < 7; ky++) {
                const float* rowp = xgc + (yloc + ky) * 16 + x0loc;
                float4 rA = *(const float4*)rowp;
                float4 rB = *(const float4*)(rowp + 4);
                float2 rC = *(const float2*)(rowp + 8);
                float xr[10] = {rA.x, rA.y, rA.z, rA.w,
                                rB.x, rB.y, rB.z, rB.w,
                                rC.x, rC.y};
#pragma unroll
                for (int kx = 0; kx < 7; kx++) {
                    int k = ky * 7 + kx;
                    ull wt01 = *(const ull*)&wt_s[k * 64 + px0];
                    ull wt23 = *(const ull*)&wt_s[k * 64 + px0 + 2];
                    fma2(acc01, wt01, pk(xr[kx], xr[kx + 1]));
                    fma2(acc23, wt23, pk(xr[kx + 2], xr[kx + 3]));
                }
            }
            float v0, v1, v2, v3;
            unpk(acc01, v0, v1);
            unpk(acc23, v2, v3);
            int gy = y0 + yloc, gx = x0 + x0loc;
            *(float4*)&out[((size_t)b * C_ + g * GC_ + ci) * NPX_ + gy * 64 + gx] =
                make_float4(v0, v1, v2, v3);
        }
    }
}

// =================================================================
extern "C" void kernel_launch(void* const* d_in, const int* in_sizes, int n_in,
                              void* d_out, int out_size) {
    const float* x     = (const float*)d_in[0];
    const float* w1    = (const float*)d_in[1];
    const float* gamma = (const float*)d_in[2];
    const float* beta  = (const float*)d_in[3];
    const float* mean  = (const float*)d_in[4];
    const float* var   = (const float*)d_in[5];
    const float* w2    = (const float*)d_in[6];
    const float* b2    = (const float*)d_in[7];
    float* out = (float*)d_out;

    cudaFuncSetAttribute(inv_kernel, cudaFuncAttributeMaxDynamicSharedMemorySize,
                         SMEM_BYTES);

    conv1_kernel<<<BN_ * NPX_ / 32, 256>>>(x, w1, gamma, beta, mean, var);
    inv_kernel<<<BN_ * 64 * GS_, 256, SMEM_BYTES>>>(x, w2, b2, out);
}

// round 3
// speedup vs baseline: 1.1220x; 1.0557x over previous
#include <cuda_runtime.h>

// Problem constants
#define BN_  4
#define C_   256
#define NPX_ 4096    // 64*64
#define O_   64
#define G_   16
#define GC_  16
#define GS_  4       // group-split factor for inv kernel (4 groups/block)

typedef unsigned long long ull;

// --------- scratch (allocation-free: __device__ global) ----------
__device__ float g_t[BN_ * NPX_ * O_];  // t tensor, [b][px][o], 4 MB

// --------- f32x2 helpers (Blackwell packed fp32) ----------
__device__ __forceinline__ ull pk(float a, float b) {
    ull r; asm("mov.b64 %0,{%1,%2};" : "=l"(r) : "f"(a), "f"(b)); return r;
}
__device__ __forceinline__ ull dupf(float a) {
    ull r; asm("mov.b64 %0,{%1,%1};" : "=l"(r) : "f"(a)); return r;
}
__device__ __forceinline__ void fma2(ull& d, ull a, ull b) {
    asm("fma.rn.f32x2 %0,%1,%2,%0;" : "+l"(d) : "l"(a), "l"(b));
}
__device__ __forceinline__ void unpk(ull v, float& a, float& b) {
    asm("mov.b64 {%0,%1},%2;" : "=f"(a), "=f"(b) : "l"(v));
}

// =================================================================
// conv1 (BN folded in-kernel): t[bpx][o] = relu(sum_c w1[o][c]*sc[o]*x + b1[o])
// Block: 64 pixels x 64 o, 256 blocks. Thread: 2px x 8o, f32x2 over o-pairs.
// =================================================================
#define WS1 68
__global__ __launch_bounds__(256) void conv1_kernel(const float* __restrict__ x,
                                                    const float* __restrict__ w1,
                                                    const float* __restrict__ gamma,
                                                    const float* __restrict__ beta,
                                                    const float* __restrict__ mean,
                                                    const float* __restrict__ var) {
    __shared__ __align__(16) float xs[32 * 64];   // [c][px]
    __shared__ __align__(16) float ws[32 * WS1];  // [c][o] (+pad), BN-folded
    __shared__ float sc_s[64], b1_s[64];

    int tid = threadIdx.x;
    int bpx0 = blockIdx.x * 64;                       // global pixel base
    const float* xb = x + (size_t)(bpx0 / NPX_) * C_ * NPX_ + (bpx0 % NPX_);

    if (tid < 64) {
        float sc = gamma[tid] * rsqrtf(var[tid] + 1e-5f);
        sc_s[tid] = sc;
        b1_s[tid] = beta[tid] - mean[tid] * sc;
    }
    __syncthreads();

    int to = tid & 7, tp = tid >> 3;
    int p0 = tp * 2, o0 = to * 8;

    ull acc0[4] = {0, 0, 0, 0};   // px p0,   o-pairs o0..o0+7
    ull acc1[4] = {0, 0, 0, 0};   // px p0+1

    for (int cc = 0; cc < C_; cc += 32) {
        __syncthreads();
        // x tile: 32c x 64px, coalesced over px
#pragma unroll
        for (int i = 0; i < 8; i++) {
            int idx = tid + i * 256;
            int c = idx >> 6, low = idx & 63;
            xs[c * 64 + low] = xb[(size_t)(cc + c) * NPX_ + low];
        }
        // w tile: 32c x 64o, read coalesced over c, scatter to [c][o], fold BN
#pragma unroll
        for (int i = 0; i < 8; i++) {
            int idx = tid + i * 256;
            int o = idx >> 5, cl = idx & 31;
            ws[cl * WS1 + o] = w1[(size_t)o * C_ + cc + cl] * sc_s[o];
        }
        __syncthreads();
#pragma unroll
        for (int c = 0; c < 32; c++) {
            float2 xv = *(const float2*)&xs[c * 64 + p0];
            ull x0d = dupf(xv.x), x1d = dupf(xv.y);
            ulonglong2 wA = *(const ulonglong2*)&ws[c * WS1 + o0];
            ulonglong2 wB = *(const ulonglong2*)&ws[c * WS1 + o0 + 4];
            fma2(acc0[0], wA.x, x0d); fma2(acc0[1], wA.y, x0d);
            fma2(acc0[2], wB.x, x0d); fma2(acc0[3], wB.y, x0d);
            fma2(acc1[0], wA.x, x1d); fma2(acc1[1], wA.y, x1d);
            fma2(acc1[2], wB.x, x1d); fma2(acc1[3], wB.y, x1d);
        }
    }

    // epilogue: bias + relu, write t (o-contiguous, float4 x2 per px)
#pragma unroll
    for (int p = 0; p < 2; p++) {
        ull* acc = p ? acc1 : acc0;
        float v[8];
#pragma unroll
        for (int j = 0; j < 4; j++) {
            float a, b;
            unpk(acc[j], a, b);
            v[2 * j]     = fmaxf(a + b1_s[o0 + 2 * j], 0.f);
            v[2 * j + 1] = fmaxf(b + b1_s[o0 + 2 * j + 1], 0.f);
        }
        float* dst = &g_t[(size_t)(bpx0 + p0 + p) * O_ + o0];
        *(float4*)dst       = make_float4(v[0], v[1], v[2], v[3]);
        *(float4*)(dst + 4) = make_float4(v[4], v[5], v[6], v[7]);
    }
}

// =================================================================
// Fused conv2 + involution, group-split 4-way (grid = 4*64*4 = 1024).
//   - conv2: wt[px][k] = sum_o w2[g*49+k][o]*t[px][o] + b2  (f32x2 k-pairs)
//   - involution: out[c] = sum_k wt[k]*x[c, shifted]        (f32x2 px-pairs)
// Involution warp layout: ci = tid&15 (low bits) so wt loads broadcast;
// xg channel stride 228 (== 4 mod 32) -> conflict-free float4 loads.
// =================================================================
#define TS_STRIDE 65           // t_s row stride (bank-conflict-free)
#define XG_CH 228              // xg channel stride (14*16 + 4 pad)
#define KPAD 56                // padded kernel count (49 -> 56)
#define SM_T   0
#define SM_XG  (64 * TS_STRIDE)
#define SM_W2  (SM_XG + 16 * XG_CH)
#define SM_WT  (SM_W2 + 64 * KPAD)
#define SM_TOT (SM_WT + KPAD * 64)
#define SMEM_BYTES (SM_TOT * 4)

__global__ __launch_bounds__(256) void inv_kernel(const float* __restrict__ x,
                                                  const float* __restrict__ w2,
                                                  const float* __restrict__ b2,
                                                  float* __restrict__ out) {
    extern __shared__ __align__(16) float sm[];
    float* t_s  = sm + SM_T;    // [64px][65]
    float* xg   = sm + SM_XG;   // [16c][228]
    float* w2s  = sm + SM_W2;   // [64o][56k]
    float* wt_s = sm + SM_WT;   // [56k][64px]

    int tid = threadIdx.x;
    int bid = blockIdx.x;
    int gs = bid & (GS_ - 1);
    int tile = (bid >> 2) & 63;
    int b = bid >> 8;
    int y0 = (tile >> 3) * 8, x0 = (tile & 7) * 8;
    const float* xb = x + (size_t)b * C_ * NPX_;

    // load t tile (64 px x 64 o), coalesced over o
#pragma unroll
    for (int i = 0; i < 16; i++) {
        int idx = tid + i * 256;
        int pxl = idx >> 6, o = idx & 63;
        int r = pxl >> 3, cx = pxl & 7;
        t_s[pxl * TS_STRIDE + o] =
            g_t[((size_t)b * NPX_ + (y0 + r) * 64 + (x0 + cx)) * O_ + o];
    }

    // conv2 thread coords: kq 0..7 (active <7), pq 0..31 -> pixels pq, pq+32
    int kq = tid >> 5, pq = tid & 31;
    // involution thread coords: ci in LOW bits (wt loads broadcast per warp)
    int ci = tid & 15, pxq = tid >> 4;
    int px0 = pxq * 4;
    int yloc = pxq >> 1, x0loc = (pxq & 1) * 4;

#pragma unroll 1
    for (int gi = 0; gi < G_ / GS_; gi++) {
        int g = gs * (G_ / GS_) + gi;
        __syncthreads();  // protect t_s (gi==0) / previous-group smem

        // stage x group halo (14x14 per channel, zero-padded)
        for (int idx = tid; idx < 16 * 196; idx += 256) {
            int c = idx / 196, rem = idx - c * 196;
            int rr = rem / 14, xx = rem - rr * 14;
            int gy = y0 + rr - 3, gx = x0 + xx - 3;
            float v = 0.f;
            if (gy >= 0 && gy < 64 && gx >= 0 && gx < 64)
                v = xb[(size_t)(g * GC_ + c) * NPX_ + gy * 64 + gx];
            xg[c * XG_CH + rr * 16 + xx] = v;
        }
        // stage w2 slice transposed: w2s[o][k]
        for (int idx = tid; idx < 64 * KPAD; idx += 256) {
            int k = idx >> 6, o = idx & 63;
            float v = (k < 49) ? w2[(size_t)(g * 49 + k) * O_ + o] : 0.f;
            w2s[o * KPAD + k] = v;
        }
        __syncthreads();

        // ---- conv2: 2 pixels x 8 k per thread, f32x2 over k-pairs ----
        if (kq < 7) {
            int k0 = kq * 8;
            ull accA[4], accB[4];
#pragma unroll
            for (int j = 0; j < 4; j++) {
                int ka = k0 + 2 * j, kb = ka + 1;
                float ba = (ka < 49) ? b2[g * 49 + ka] : 0.f;
                float bb = (kb < 49) ? b2[g * 49 + kb] : 0.f;
                accA[j] = pk(ba, bb);
                accB[j] = accA[j];
            }
            const float* w2p = w2s + k0;
            const float* tp0 = t_s + pq * TS_STRIDE;
            const float* tp1 = t_s + (pq + 32) * TS_STRIDE;
#pragma unroll 8
            for (int o = 0; o < 64; o++) {
                ulonglong2 w01 = *(const ulonglong2*)(w2p + o * KPAD);
                ulonglong2 w23 = *(const ulonglong2*)(w2p + o * KPAD + 4);
                ull da = dupf(tp0[o]);
                ull db = dupf(tp1[o]);
                fma2(accA[0], w01.x, da); fma2(accA[1], w01.y, da);
                fma2(accA[2], w23.x, da); fma2(accA[3], w23.y, da);
                fma2(accB[0], w01.x, db); fma2(accB[1], w01.y, db);
                fma2(accB[2], w23.x, db); fma2(accB[3], w23.y, db);
            }
#pragma unroll
            for (int j = 0; j < 4; j++) {
                float a0, a1, b0, b1;
                unpk(accA[j], a0, a1);
                unpk(accB[j], b0, b1);
                wt_s[(k0 + 2 * j) * 64 + pq]          = a0;
                wt_s[(k0 + 2 * j + 1) * 64 + pq]      = a1;
                wt_s[(k0 + 2 * j) * 64 + pq + 32]     = b0;
                wt_s[(k0 + 2 * j + 1) * 64 + pq + 32] = b1;
            }
        }
        __syncthreads();

        // ---- involution: 4 adjacent-x pixels x 1 channel per thread ----
        {
            ull acc01 = 0ull, acc23 = 0ull;
            const float* xgc = xg + ci * XG_CH + yloc * 16 + x0loc;
            const float* wtp = wt_s + px0;
#pragma unroll
            for (int ky = 0; ky < 7; ky++) {
                const float* rowp = xgc + ky * 16;
                float4 rA = *(const float4*)rowp;
                float4 rB = *(const float4*)(rowp + 4);
                float2 rC = *(const float2*)(rowp + 8);
                float xr[10] = {rA.x, rA.y, rA.z, rA.w,
                                rB.x, rB.y, rB.z, rB.w,
                                rC.x, rC.y};
                // pre-pack adjacent pairs once; reused by both accumulators
                ull xp[9];
#pragma unroll
                for (int j = 0; j < 9; j++) xp[j] = pk(xr[j], xr[j + 1]);
#pragma unroll
                for (int kx = 0; kx < 7; kx++) {
                    const float* wk = wtp + (ky * 7 + kx) * 64;
                    fma2(acc01, *(const ull*)wk,       xp[kx]);
                    fma2(acc23, *(const ull*)(wk + 2), xp[kx + 2]);
                }
            }
            float v0, v1, v2, v3;
            unpk(acc01, v0, v1);
            unpk(acc23, v2, v3);
            int gy = y0 + yloc, gx = x0 + x0loc;
            *(float4*)&out[((size_t)b * C_ + g * GC_ + ci) * NPX_ + gy * 64 + gx] =
                make_float4(v0, v1, v2, v3);
        }
    }
}

// =================================================================
extern "C" void kernel_launch(void* const* d_in, const int* in_sizes, int n_in,
                              void* d_out, int out_size) {
    const float* x     = (const float*)d_in[0];
    const float* w1    = (const float*)d_in[1];
    const float* gamma = (const float*)d_in[2];
    const float* beta  = (const float*)d_in[3];
    const float* mean  = (const float*)d_in[4];
    const float* var   = (const float*)d_in[5];
    const float* w2    = (const float*)d_in[6];
    const float* b2    = (const float*)d_in[7];
    float* out = (float*)d_out;

    cudaFuncSetAttribute(inv_kernel, cudaFuncAttributeMaxDynamicSharedMemorySize,
                         SMEM_BYTES);

    conv1_kernel<<<BN_ * NPX_ / 64, 256>>>(x, w1, gamma, beta, mean, var);
    inv_kernel<<<BN_ * 64 * GS_, 256, SMEM_BYTES>>>(x, w2, b2, out);
}

// round 5
// speedup vs baseline: 1.1864x; 1.0574x over previous
#include <cuda_runtime.h>

// Problem constants
#define BN_  4
#define C_   256
#define NPX_ 4096    // 64*64
#define O_   64
#define G_   16
#define GC_  16
#define GS_  4       // group-split factor for inv kernel (4 groups/block)
#define KPAD 56      // padded kernel count (49 -> 56)

typedef unsigned long long ull;

// --------- scratch (allocation-free: __device__ globals) ----------
__device__ float g_t[BN_ * NPX_ * O_];     // t tensor, [b][px][o], 4 MB
__device__ float g_w1t[C_ * O_];           // [c][o], BN-folded
__device__ float g_b1[O_];                 // BN-folded bias
__device__ float g_w2t[G_ * O_ * KPAD];    // [g][o][k], zero-padded k>=49

// --------- f32x2 helpers (Blackwell packed fp32) ----------
__device__ __forceinline__ ull pk(float a, float b) {
    ull r; asm("mov.b64 %0,{%1,%2};" : "=l"(r) : "f"(a), "f"(b)); return r;
}
__device__ __forceinline__ ull dupf(float a) {
    ull r; asm("mov.b64 %0,{%1,%1};" : "=l"(r) : "f"(a)); return r;
}
__device__ __forceinline__ void fma2(ull& d, ull a, ull b) {
    asm("fma.rn.f32x2 %0,%1,%2,%0;" : "+l"(d) : "l"(a), "l"(b));
}
__device__ __forceinline__ void unpk(ull v, float& a, float& b) {
    asm("mov.b64 {%0,%1},%2;" : "=f"(a), "=f"(b) : "l"(v));
}

// =================================================================
// Prep: BN-fold + transpose w1 -> [c][o]; transpose w2 -> [g][o][k] padded.
// =================================================================
__global__ __launch_bounds__(256) void prep_kernel(const float* __restrict__ w1,
                                                   const float* __restrict__ gamma,
                                                   const float* __restrict__ beta,
                                                   const float* __restrict__ mean,
                                                   const float* __restrict__ var,
                                                   const float* __restrict__ w2) {
    int tid = blockIdx.x * 256 + threadIdx.x;
    int nthr = gridDim.x * 256;

    // w1t[c][o] = w1[o][c] * scale[o]
    for (int i = tid; i < C_ * O_; i += nthr) {
        int c = i >> 6, o = i & 63;
        float sc = gamma[o] * rsqrtf(var[o] + 1e-5f);
        g_w1t[i] = w1[(size_t)o * C_ + c] * sc;
    }
    if (tid < O_) {
        float sc = gamma[tid] * rsqrtf(var[tid] + 1e-5f);
        g_b1[tid] = beta[tid] - mean[tid] * sc;
    }
    // w2t[g][o][k] = w2[g*49+k][o]  (coalesced loads over o)
    for (int i = tid; i < G_ * 49 * O_; i += nthr) {
        int o = i & 63;
        int gk = i >> 6;            // g*49 + k
        int g = gk / 49, k = gk - g * 49;
        g_w2t[((size_t)(g * O_ + o)) * KPAD + k] = w2[i];
    }
    // zero-pad k = 49..55
    for (int i = tid; i < G_ * O_ * (KPAD - 49); i += nthr) {
        int kk = i % (KPAD - 49);
        int go = i / (KPAD - 49);
        g_w2t[(size_t)go * KPAD + 49 + kk] = 0.f;
    }
}

// =================================================================
// conv1: t[bpx][o] = relu(sum_c w1t[c][o]*x + b1[o])
// Block: 64 pixels x 64 o, 256 blocks. Thread: 2px x 8o, f32x2 over o-pairs.
// Staging: both x and w are stride-1 stores (conflict-free).
// =================================================================
#define WS1 68
__global__ __launch_bounds__(256) void conv1_kernel(const float* __restrict__ x) {
    __shared__ __align__(16) float xs[32 * 64];   // [c][px]
    __shared__ __align__(16) float ws[32 * WS1];  // [c][o] (+pad)

    int tid = threadIdx.x;
    int bpx0 = blockIdx.x * 64;                       // global pixel base
    const float* xb = x + (size_t)(bpx0 / NPX_) * C_ * NPX_ + (bpx0 % NPX_);

    int to = tid & 7, tp = tid >> 3;
    int p0 = tp * 2, o0 = to * 8;

    ull acc0[4] = {0, 0, 0, 0};   // px p0,   o-pairs o0..o0+7
    ull acc1[4] = {0, 0, 0, 0};   // px p0+1

    for (int cc = 0; cc < C_; cc += 32) {
        __syncthreads();
        // x tile: 32c x 64px, coalesced loads + stride-1 stores
#pragma unroll
        for (int i = 0; i < 8; i++) {
            int idx = tid + i * 256;
            int c = idx >> 6, low = idx & 63;
            xs[c * 64 + low] = xb[(size_t)(cc + c) * NPX_ + low];
        }
        // w tile: 32c x 64o from pre-transposed w1t: coalesced + stride-1
#pragma unroll
        for (int i = 0; i < 8; i++) {
            int idx = tid + i * 256;
            int c = idx >> 6, o = idx & 63;
            ws[c * WS1 + o] = g_w1t[(cc + c) * O_ + o];
        }
        __syncthreads();
#pragma unroll
        for (int c = 0; c < 32; c++) {
            float2 xv = *(const float2*)&xs[c * 64 + p0];
            ull x0d = dupf(xv.x), x1d = dupf(xv.y);
            ulonglong2 wA = *(const ulonglong2*)&ws[c * WS1 + o0];
            ulonglong2 wB = *(const ulonglong2*)&ws[c * WS1 + o0 + 4];
            fma2(acc0[0], wA.x, x0d); fma2(acc0[1], wA.y, x0d);
            fma2(acc0[2], wB.x, x0d); fma2(acc0[3], wB.y, x0d);
            fma2(acc1[0], wA.x, x1d); fma2(acc1[1], wA.y, x1d);
            fma2(acc1[2], wB.x, x1d); fma2(acc1[3], wB.y, x1d);
        }
    }

    // epilogue: bias + relu, write t (o-contiguous, float4 x2 per px)
#pragma unroll
    for (int p = 0; p < 2; p++) {
        ull* acc = p ? acc1 : acc0;
        float v[8];
#pragma unroll
        for (int j = 0; j < 4; j++) {
            float a, b;
            unpk(acc[j], a, b);
            v[2 * j]     = fmaxf(a + g_b1[o0 + 2 * j], 0.f);
            v[2 * j + 1] = fmaxf(b + g_b1[o0 + 2 * j + 1], 0.f);
        }
        float* dst = &g_t[(size_t)(bpx0 + p0 + p) * O_ + o0];
        *(float4*)dst       = make_float4(v[0], v[1], v[2], v[3]);
        *(float4*)(dst + 4) = make_float4(v[4], v[5], v[6], v[7]);
    }
}

// =================================================================
// Fused conv2 + involution, group-split 4-way (grid = 4*64*4 = 1024).
//   - conv2: wt[px][k] = sum_o w2t[g][o][k]*t[px][o] + b2  (f32x2 k-pairs)
//   - involution: out[c] = sum_k wt[k]*x[c, shifted]        (f32x2 px-pairs)
// All staging paths stride-1; wt reads are LDS.128 warp-broadcast.
// =================================================================
#define TS_STRIDE 65           // t_s row stride (bank-conflict-free)
#define XG_CH 228              // xg channel stride (14*16 + 4 pad)
#define SM_T   0
#define SM_XG  (64 * TS_STRIDE)
#define SM_W2  (SM_XG + 16 * XG_CH)
#define SM_WT  (SM_W2 + 64 * KPAD)
#define SM_TOT (SM_WT + KPAD * 64)
#define SMEM_BYTES (SM_TOT * 4)

__global__ __launch_bounds__(256) void inv_kernel(const float* __restrict__ x,
                                                  const float* __restrict__ b2,
                                                  float* __restrict__ out) {
    extern __shared__ __align__(16) float sm[];
    float* t_s  = sm + SM_T;    // [64px][65]
    float* xg   = sm + SM_XG;   // [16c][228]
    float* w2s  = sm + SM_W2;   // [64o][56k]
    float* wt_s = sm + SM_WT;   // [56k][64px]

    int tid = threadIdx.x;
    int bid = blockIdx.x;
    int gs = bid & (GS_ - 1);
    int tile = (bid >> 2) & 63;
    int b = bid >> 8;
    int y0 = (tile >> 3) * 8, x0 = (tile & 7) * 8;
    const float* xb = x + (size_t)b * C_ * NPX_;

    // load t tile (64 px x 64 o), coalesced over o, stride-1 stores
#pragma unroll
    for (int i = 0; i < 16; i++) {
        int idx = tid + i * 256;
        int pxl = idx >> 6, o = idx & 63;
        int r = pxl >> 3, cx = pxl & 7;
        t_s[pxl * TS_STRIDE + o] =
            g_t[((size_t)b * NPX_ + (y0 + r) * 64 + (x0 + cx)) * O_ + o];
    }

    // conv2 thread coords: kq 0..7 (active <7), pq 0..31 -> pixels pq, pq+32
    int kq = tid >> 5, pq = tid & 31;
    // involution thread coords: ci in LOW bits (wt loads broadcast per warp)
    int ci = tid & 15, pxq = tid >> 4;
    int px0 = pxq * 4;
    int yloc = pxq >> 1, x0loc = (pxq & 1) * 4;

#pragma unroll 1
    for (int gi = 0; gi < G_ / GS_; gi++) {
        int g = gs * (G_ / GS_) + gi;
        __syncthreads();  // protect t_s (gi==0) / previous-group smem

        // stage x group halo (14x14 per channel, zero-padded)
        for (int idx = tid; idx < 16 * 196; idx += 256) {
            int c = idx / 196, rem = idx - c * 196;
            int rr = rem / 14, xx = rem - rr * 14;
            int gy = y0 + rr - 3, gx = x0 + xx - 3;
            float v = 0.f;
            if (gy >= 0 && gy < 64 && gx >= 0 && gx < 64)
                v = xb[(size_t)(g * GC_ + c) * NPX_ + gy * 64 + gx];
            xg[c * XG_CH + rr * 16 + xx] = v;
        }
        // stage w2 slice: pre-transposed -> pure stride-1 copy (conflict-free)
        {
            const float* src = g_w2t + (size_t)g * O_ * KPAD;
#pragma unroll
            for (int i = 0; i < 14; i++)
                w2s[tid + i * 256] = src[tid + i * 256];
        }
        __syncthreads();

        // ---- conv2: 2 pixels x 8 k per thread, f32x2 over k-pairs ----
        if (kq < 7) {
            int k0 = kq * 8;
            ull accA[4], accB[4];
#pragma unroll
            for (int j = 0; j < 4; j++) {
                int ka = k0 + 2 * j, kb = ka + 1;
                float ba = (ka < 49) ? b2[g * 49 + ka] : 0.f;
                float bb = (kb < 49) ? b2[g * 49 + kb] : 0.f;
                accA[j] = pk(ba, bb);
                accB[j] = accA[j];
            }
            const float* w2p = w2s + k0;
            const float* tp0 = t_s + pq * TS_STRIDE;
            const float* tp1 = t_s + (pq + 32) * TS_STRIDE;
#pragma unroll 8
            for (int o = 0; o < 64; o++) {
                ulonglong2 w01 = *(const ulonglong2*)(w2p + o * KPAD);
                ulonglong2 w23 = *(const ulonglong2*)(w2p + o * KPAD + 4);
                ull da = dupf(tp0[o]);
                ull db = dupf(tp1[o]);
                fma2(accA[0], w01.x, da); fma2(accA[1], w01.y, da);
                fma2(accA[2], w23.x, da); fma2(accA[3], w23.y, da);
                fma2(accB[0], w01.x, db); fma2(accB[1], w01.y, db);
                fma2(accB[2], w23.x, db); fma2(accB[3], w23.y, db);
            }
#pragma unroll
            for (int j = 0; j < 4; j++) {
                float a0, a1, b0, b1;
                unpk(accA[j], a0, a1);
                unpk(accB[j], b0, b1);
                wt_s[(k0 + 2 * j) * 64 + pq]          = a0;
                wt_s[(k0 + 2 * j + 1) * 64 + pq]      = a1;
                wt_s[(k0 + 2 * j) * 64 + pq + 32]     = b0;
                wt_s[(k0 + 2 * j + 1) * 64 + pq + 32] = b1;
            }
        }
        __syncthreads();

        // ---- involution: 4 adjacent-x pixels x 1 channel per thread ----
        {
            ull acc01 = 0ull, acc23 = 0ull;
            const float* xgc = xg + ci * XG_CH + yloc * 16 + x0loc;
            const float* wtp = wt_s + px0;
#pragma unroll
            for (int ky = 0; ky < 7; ky++) {
                const float* rowp = xgc + ky * 16;
                float4 rA = *(const float4*)rowp;
                float4 rB = *(const float4*)(rowp + 4);
                float2 rC = *(const float2*)(rowp + 8);
                float xr[10] = {rA.x, rA.y, rA.z, rA.w,
                                rB.x, rB.y, rB.z, rB.w,
                                rC.x, rC.y};
                // pre-pack adjacent pairs once; reused by both accumulators
                ull xp[9];
#pragma unroll
                for (int j = 0; j < 9; j++) xp[j] = pk(xr[j], xr[j + 1]);
#pragma unroll
                for (int kx = 0; kx < 7; kx++) {
                    // one LDS.128: covers both px pairs of the quad
                    ulonglong2 wq = *(const ulonglong2*)(wtp + (ky * 7 + kx) * 64);
                    fma2(acc01, wq.x, xp[kx]);
                    fma2(acc23, wq.y, xp[kx + 2]);
                }
            }
            float v0, v1, v2, v3;
            unpk(acc01, v0, v1);
            unpk(acc23, v2, v3);
            int gy = y0 + yloc, gx = x0 + x0loc;
            *(float4*)&out[((size_t)b * C_ + g * GC_ + ci) * NPX_ + gy * 64 + gx] =
                make_float4(v0, v1, v2, v3);
        }
    }
}

// =================================================================
extern "C" void kernel_launch(void* const* d_in, const int* in_sizes, int n_in,
                              void* d_out, int out_size) {
    const float* x     = (const float*)d_in[0];
    const float* w1    = (const float*)d_in[1];
    const float* gamma = (const float*)d_in[2];
    const float* beta  = (const float*)d_in[3];
    const float* mean  = (const float*)d_in[4];
    const float* var   = (const float*)d_in[5];
    const float* w2    = (const float*)d_in[6];
    const float* b2    = (const float*)d_in[7];
    float* out = (float*)d_out;

    cudaFuncSetAttribute(inv_kernel, cudaFuncAttributeMaxDynamicSharedMemorySize,
                         SMEM_BYTES);

    prep_kernel<<<64, 256>>>(w1, gamma, beta, mean, var, w2);
    conv1_kernel<<<BN_ * NPX_ / 64, 256>>>(x);
    inv_kernel<<<BN_ * 64 * GS_, 256, SMEM_BYTES>>>(x, b2, out);
}